// round 6
// baseline (speedup 1.0000x reference)
#include <cuda_runtime.h>

#define NCLS 32000
#define NTHREADS 320          // 10 warps; 320*4*25 == 32000 exactly
#define ITERS 25

__device__ int g_tgt_is32;    // 1 if target buffer is int32-packed, 0 if int64

// Zero the output scalar and detect target dtype layout.
// int64 layout: int32 words are (lo, hi) pairs, hi == 0 always (targets < 32000).
// int32 layout: odd words are random targets in [0, 32000) -> almost surely nonzero.
__global__ void init_detect_kernel(const int* __restrict__ tgt_words,
                                   float* __restrict__ out, int n_rows) {
    __shared__ int s_any;
    if (threadIdx.x == 0) s_any = 0;
    __syncthreads();
    int local = 0;
    for (int i = 1 + 2 * (int)threadIdx.x; i < n_rows; i += 2 * (int)blockDim.x)
        local |= tgt_words[i];
    if (local) atomicOr(&s_any, 1);
    __syncthreads();
    if (threadIdx.x == 0) {
        g_tgt_is32 = (s_any != 0) ? 1 : 0;
        *out = 0.0f;
    }
}

__global__ __launch_bounds__(NTHREADS)
void focal_loss_kernel(const float* __restrict__ x,
                       const void* __restrict__ tgt,
                       float* __restrict__ out) {
    const int row = blockIdx.x;
    const int t   = threadIdx.x;
    const float4* __restrict__ xr =
        reinterpret_cast<const float4*>(x + (size_t)row * NCLS);

    // 4 independent accumulators (ILP on the FADD/MUFU chains)
    float s0 = 0.f, s1 = 0.f, s2 = 0.f, s3 = 0.f;
    #pragma unroll 5
    for (int i = 0; i < ITERS; i++) {
        float4 v = xr[t + i * NTHREADS];     // coalesced 16B per lane
        s0 += __expf(v.x);
        s1 += __expf(v.y);
        s2 += __expf(v.z);
        s3 += __expf(v.w);
    }
    float s = (s0 + s1) + (s2 + s3);

    // warp reduce
    #pragma unroll
    for (int o = 16; o > 0; o >>= 1)
        s += __shfl_xor_sync(0xffffffffu, s, o);

    __shared__ float ws[NTHREADS / 32];
    if ((t & 31) == 0) ws[t >> 5] = s;
    __syncthreads();

    if (t == 0) {
        float tot = 0.f;
        #pragma unroll
        for (int w = 0; w < NTHREADS / 32; w++) tot += ws[w];

        long long ti;
        if (g_tgt_is32) ti = (long long)((const int*)tgt)[row];
        else            ti = ((const long long*)tgt)[row];

        float xt    = x[(size_t)row * NCLS + ti];   // L2 hit (row just streamed)
        float logpt = xt - logf(tot);               // log_softmax at target
        float pt    = expf(logpt);

        // GAMMA_HIGH == GAMMA_MID == 3, GAMMA_LOW == 5  ->  gamma = pt<0.2 ? 5 : 3
        float u  = 1.0f - pt;
        float u3 = u * u * u;
        float w  = (pt < 0.2f) ? u3 * u * u : u3;

        atomicAdd(out, -w * logpt);
    }
}

extern "C" void kernel_launch(void* const* d_in, const int* in_sizes, int n_in,
                              void* d_out, int out_size) {
    const float* x   = (const float*)d_in[0];
    const void*  tgt = d_in[1];
    float*       out = (float*)d_out;
    const int n_rows = in_sizes[1];     // 8192 element count either dtype

    init_detect_kernel<<<1, 256>>>((const int*)tgt, out, n_rows);
    focal_loss_kernel<<<n_rows, NTHREADS>>>(x, tgt, out);
}